// round 16
// baseline (speedup 1.0000x reference)
#include <cuda_runtime.h>
#include <math.h>

#define CC 256
#define HW 65536
#define NSWMAX 10
#define ROTTHR 2e-7f   // relative off-diag threshold^2

// ---- scratch (static device arrays; no allocation anywhere) ----
__device__ float g_B[CC * HW];   // 64MB: per-channel working matrix, column-major
__device__ float g_T[CC * HW];   // 64MB: T = diag(f) * B^T A
__device__ float g_R[CC * HW];   // 64MB: recon = B * T
__device__ float g_mean[CC];
__device__ float g_max[CC];
__device__ int   g_k[CC];
__device__ float g_fact[CC * CC];
__device__ float g_cat[2 * HW];

__device__ __forceinline__ float warp_sum(float a) {
#pragma unroll
    for (int o = 16; o > 0; o >>= 1) a += __shfl_xor_sync(0xFFFFFFFFu, a, o);
    return a;
}

// ---------------- stage 0: per-channel mean & max over HxW ----------------
__global__ void k_stats(const float* __restrict__ x) {
    int c = blockIdx.x, t = threadIdx.x;
    const float* xc = x + (size_t)c * HW;
    double s = 0.0;
    float m = -3.4e38f;
    for (int i = t; i < HW; i += 256) {
        float v = xc[i];
        s += (double)v;
        m = fmaxf(m, v);
    }
    __shared__ double ss[256];
    __shared__ float  sm[256];
    ss[t] = s; sm[t] = m;
    __syncthreads();
    for (int o = 128; o > 0; o >>= 1) {
        if (t < o) { ss[t] += ss[t + o]; sm[t] = fmaxf(sm[t], sm[t + o]); }
        __syncthreads();
    }
    if (t == 0) {
        g_mean[c] = (float)(ss[0] / (double)HW);
        g_max[c]  = sm[0];
    }
}

// ---------------- stage 1: channel attention -> k[c] ----------------
__global__ void k_att(const float* __restrict__ w1, const float* __restrict__ w2,
                      const int* __restrict__ kvp) {
    int t = threadIdx.x;
    __shared__ float  mu[256], mx[256];
    __shared__ double hA[16], hM[16];
    __shared__ double sy[256];
    __shared__ double ymin, ymax;
    mu[t] = g_mean[t]; mx[t] = g_max[t];
    __syncthreads();
    if (t < 16) {
        double a = 0.0, b = 0.0;
        for (int c2 = 0; c2 < 256; c2++) {
            double w = (double)w1[t * 256 + c2];
            a += w * (double)mu[c2];
            b += w * (double)mx[c2];
        }
        hA[t] = a > 0.0 ? a : 0.0;   // relu
        hM[t] = b > 0.0 ? b : 0.0;
    }
    __syncthreads();
    {
        double acc = 0.0;
        for (int r = 0; r < 16; r++)
            acc += (double)w2[t * 16 + r] * (hA[r] + hM[r]);
        sy[t] = 1.0 / (1.0 + exp(-acc));     // sigmoid(y_avg + y_max)
    }
    __syncthreads();
    if (t == 0) {
        double mn = sy[0], mv = sy[0];
        for (int i = 1; i < 256; i++) { mn = fmin(mn, sy[i]); mv = fmax(mv, sy[i]); }
        ymin = mn; ymax = mv;
    }
    __syncthreads();
    // kv hedge: accept int32 or float32 bit patterns
    int iv = *kvp;
    float fv = __int_as_float(iv);
    double kvd = (iv >= 0 && iv <= 1000000) ? (double)iv : (double)fv;
    double yc = (sy[t] - ymin) / (ymax - ymin + 1e-20);
    int k = (int)floor(256.0 * kvd * yc);
    if (k < 0) k = 0;
    if (k > 256) k = 256;
    g_k[t] = k;
}

// ---------------- stage 2: transpose x -> column-major B ----------------
__global__ void k_tr(const float* __restrict__ x) {
    __shared__ float tile[32][33];
    int c = blockIdx.z;
    int i0 = blockIdx.y * 32, j0 = blockIdx.x * 32;
    int tx = threadIdx.x, ty = threadIdx.y;
    const float* xc = x + (size_t)c * HW;
    float* bc = g_B + (size_t)c * HW;
#pragma unroll
    for (int m = 0; m < 4; m++)
        tile[ty + 8 * m][tx] = xc[(i0 + ty + 8 * m) * 256 + j0 + tx];
    __syncthreads();
#pragma unroll
    for (int m = 0; m < 4; m++)
        bc[(j0 + ty + 8 * m) * 256 + i0 + tx] = tile[tx][ty + 8 * m];
}

// load/store a 256-float column (8 per lane) as 2x float4
#define LDCOL(V, PTR)                                                          \
    { float4 _a = (PTR)[lane * 2], _b = (PTR)[lane * 2 + 1];                   \
      V[0]=_a.x; V[1]=_a.y; V[2]=_a.z; V[3]=_a.w;                              \
      V[4]=_b.x; V[5]=_b.y; V[6]=_b.z; V[7]=_b.w; }
#define STCOL(PTR, V)                                                          \
    { (PTR)[lane * 2]     = make_float4(V[0], V[1], V[2], V[3]);               \
      (PTR)[lane * 2 + 1] = make_float4(V[4], V[5], V[6], V[7]); }

// Jacobi rotation on columns (VI,VJ) with exact Gram-matrix tracking:
// NI/NJ are diag entries, EIJ the pivot; (EA,EB) and (EC,ED) are the
// (E[i][k],E[j][k]) cross terms for the two other columns k.
#define ROT4(VI, VJ, NI, NJ, EIJ, EA, EB, EC, ED)                              \
    if ((EIJ) * (EIJ) > ROTTHR * (NI) * (NJ)) {                                \
        float tau = ((NJ) - (NI)) / (2.0f * (EIJ));                            \
        float tt  = copysignf(1.0f, tau) / (fabsf(tau) + sqrtf(1.0f + tau * tau)); \
        float cc  = 1.0f / sqrtf(1.0f + tt * tt);                              \
        float ss  = tt * cc;                                                   \
        _Pragma("unroll")                                                      \
        for (int m = 0; m < 8; m++) {                                          \
            float xp = VI[m];                                                  \
            VI[m] = fmaf(cc, xp, -ss * VJ[m]);                                 \
            VJ[m] = fmaf(ss, xp,  cc * VJ[m]);                                 \
        }                                                                      \
        (NI) -= tt * (EIJ); (NJ) += tt * (EIJ); (EIJ) = 0.0f;                  \
        float _ta = (EA); (EA) = fmaf(cc, _ta, -ss * (EB)); (EB) = fmaf(ss, _ta, cc * (EB)); \
        float _tc = (EC); (EC) = fmaf(cc, _tc, -ss * (ED)); (ED) = fmaf(ss, _tc, cc * (ED)); \
        hit = true;                                                            \
    }

// 6 pairwise dots of v0..v3, one interleaved warp reduction
#define DOTS6(V0, V1, V2, V3)                                                  \
    e01 = 0.f; e02 = 0.f; e03 = 0.f; e12 = 0.f; e13 = 0.f; e23 = 0.f;         \
    _Pragma("unroll")                                                          \
    for (int m = 0; m < 8; m++) {                                              \
        e01 = fmaf(V0[m], V1[m], e01); e02 = fmaf(V0[m], V2[m], e02);          \
        e03 = fmaf(V0[m], V3[m], e03); e12 = fmaf(V1[m], V2[m], e12);          \
        e13 = fmaf(V1[m], V3[m], e13); e23 = fmaf(V2[m], V3[m], e23);          \
    }                                                                          \
    _Pragma("unroll")                                                          \
    for (int o = 16; o > 0; o >>= 1) {                                         \
        e01 += __shfl_xor_sync(0xFFFFFFFFu, e01, o);                           \
        e02 += __shfl_xor_sync(0xFFFFFFFFu, e02, o);                           \
        e03 += __shfl_xor_sync(0xFFFFFFFFu, e03, o);                           \
        e12 += __shfl_xor_sync(0xFFFFFFFFu, e12, o);                           \
        e13 += __shfl_xor_sync(0xFFFFFFFFu, e13, o);                           \
        e23 += __shfl_xor_sync(0xFFFFFFFFu, e23, o);                           \
    }

// full 4x4 micro-solve rotation sequence (cross pairs first, then in-pair)
#define SOLVE4(V0, V1, V2, V3)                                                 \
    ROT4(V0, V2, n0, n2, e02, e01, e12, e03, e23);                             \
    ROT4(V1, V3, n1, n3, e13, e01, e03, e12, e23);                             \
    ROT4(V0, V3, n0, n3, e03, e01, e13, e02, e23);                             \
    ROT4(V1, V2, n1, n2, e12, e01, e02, e13, e23);                             \
    ROT4(V0, V1, n0, n1, e01, e02, e12, e03, e13);                             \
    ROT4(V2, V3, n2, n3, e23, e02, e03, e12, e13);

// ---------------- stage 3: blocked one-sided Jacobi (Hestenes), no V ----------------
// 512 threads (16 warps), 2 CTAs/SM. 8 blocks of 32 columns.
// Every round is a 4-column Gram micro-solve: 6 dots in ONE interleaved warp
// reduction, then up to 6 threshold-guarded rotations with exact analytic
// updates of the 4x4 Gram matrix (no second dot phase).
// Intra-block: 16 two-column entities, 15 tournament rounds x 8 matchups.
// Cross-block: warp holds reg cols (w, w+16); round r claims smem col pair
// (2*qp, 2*qp+1), qp=(w+r)&15 -> 16 rounds cover all reg x smem pairs.
// Clean-pair matrix skips fully-converged block pairs.
__global__ void __launch_bounds__(512, 2) k_jacobi() {
    int c = blockIdx.x;
    float* Bg = g_B + (size_t)c * HW;
    int t = threadIdx.x, lane = t & 31, w = t >> 5;   // w in 0..15

    __shared__ float sj[8192];     // 32KB: one 32-column block
    __shared__ float snj[32];      // column norms^2 of smem block
    __shared__ int s_flag;         // any rotation this sweep
    __shared__ int s_dirty;        // any rotation this phase
    __shared__ int s_any;          // any rotation this bi iteration
    __shared__ int s_skip;         // whole bi iteration clean
    __shared__ unsigned char s_clean[8][8];

    if (t < 64) s_clean[t >> 3][t & 7] = 0;
    __syncthreads();

    for (int sweep = 0; sweep < NSWMAX; sweep++) {
        if (t == 0) s_flag = 0;
        __syncthreads();
        for (int bi = 0; bi < 8; bi++) {
            // ---- whole-iteration skip check
            if (t == 0) {
                int ac = s_clean[bi][bi];
                for (int bj = bi + 1; bj < 8; bj++) ac &= s_clean[bi][bj];
                s_skip = ac;
            }
            __syncthreads();
            if (s_skip) continue;   // uniform

            // ---- load block bi: warp w loads cols w, w+16 + computes norms
#pragma unroll
            for (int h = 0; h < 2; h++) {
                int col = w + 16 * h;
                const float4* src = (const float4*)(Bg + (bi * 32 + col) * 256);
                float4* dst = (float4*)(sj + col * 256);
                float4 v0 = src[lane * 2], v1 = src[lane * 2 + 1];
                dst[lane * 2] = v0; dst[lane * 2 + 1] = v1;
                float a = v0.x*v0.x + v0.y*v0.y + v0.z*v0.z + v0.w*v0.w
                        + v1.x*v1.x + v1.y*v1.y + v1.z*v1.z + v1.w*v1.w;
                a = warp_sum(a);
                if (lane == 0) snj[col] = a;
            }
            if (t == 0) { s_any = 0; s_dirty = 0; }
            __syncthreads();

            // ---- intra-block: tournament over 16 two-column entities
            int do_intra = (s_clean[bi][bi] == 0);   // uniform, stable
            if (do_intra) {
                for (int r = 0; r < 15; r++) {
                    if (w < 8) {
                        int p = (w == 0) ? 0 : 1 + (w - 1 + r) % 15;
                        int q = 1 + (14 - w + r) % 15;
                        int ca = 2 * p, cb = 2 * p + 1;
                        int cc2 = 2 * q, cd = 2 * q + 1;
                        float4* Pa = (float4*)(sj + ca * 256);
                        float4* Pb = (float4*)(sj + cb * 256);
                        float4* Qa = (float4*)(sj + cc2 * 256);
                        float4* Qb = (float4*)(sj + cd * 256);
                        float v0[8], v1[8], v2[8], v3[8];
                        LDCOL(v0, Pa); LDCOL(v1, Pb); LDCOL(v2, Qa); LDCOL(v3, Qb);
                        float n0 = snj[ca], n1 = snj[cb], n2 = snj[cc2], n3 = snj[cd];
                        float e01, e02, e03, e12, e13, e23;
                        DOTS6(v0, v1, v2, v3);
                        bool hit = false;
                        SOLVE4(v0, v1, v2, v3);
                        if (hit) {
                            STCOL(Pa, v0); STCOL(Pb, v1);
                            STCOL(Qa, v2); STCOL(Qb, v3);
                        }
                        if (lane == 0) {
                            snj[ca] = n0; snj[cb] = n1; snj[cc2] = n2; snj[cd] = n3;
                            if (hit) { s_flag = 1; s_any = 1; s_dirty = 1; }
                        }
                    }
                    __syncthreads();
                }
                // clean-matrix update from intra result (s_dirty stable post-barrier)
                if (t == 0) {
                    if (s_dirty) {
                        for (int k2 = 0; k2 < 8; k2++) { s_clean[bi][k2] = 0; s_clean[k2][bi] = 0; }
                    } else {
                        s_clean[bi][bi] = 1;
                    }
                }
                // settled by the barrier at top of bj loop below
            }

            // ---- move cols w and w+16 of bi into registers (exact norms)
            float rp0[8], rp1[8], app0, app1;
            {
                const float4* c0 = (const float4*)(sj + w * 256);
                LDCOL(rp0, c0);
                float a = 0.f;
#pragma unroll
                for (int m = 0; m < 8; m++) a = fmaf(rp0[m], rp0[m], a);
                app0 = warp_sum(a);
                const float4* c1 = (const float4*)(sj + (w + 16) * 256);
                LDCOL(rp1, c1);
                float b = 0.f;
#pragma unroll
                for (int m = 0; m < 8; m++) b = fmaf(rp1[m], rp1[m], b);
                app1 = warp_sum(b);
            }

            // ---- cross-block phases
            for (int bj = bi + 1; bj < 8; bj++) {
                __syncthreads();   // settle clean-matrix writes from prior phase/intra
                int do_cross = (s_clean[bi][bj] == 0);   // uniform
                if (!do_cross) continue;

                // load bj (own cols — same-warp ordering vs. prior reads)
#pragma unroll
                for (int h = 0; h < 2; h++) {
                    int col = w + 16 * h;
                    const float4* src = (const float4*)(Bg + (bj * 32 + col) * 256);
                    float4* dst = (float4*)(sj + col * 256);
                    float4 v0 = src[lane * 2], v1 = src[lane * 2 + 1];
                    dst[lane * 2] = v0; dst[lane * 2 + 1] = v1;
                    float a = v0.x*v0.x + v0.y*v0.y + v0.z*v0.z + v0.w*v0.w
                            + v1.x*v1.x + v1.y*v1.y + v1.z*v1.z + v1.w*v1.w;
                    a = warp_sum(a);
                    if (lane == 0) snj[col] = a;
                }
                if (t == 0) s_dirty = 0;
                __syncthreads();

                // 16 rounds; warp claims smem col pair (2*qp, 2*qp+1)
                for (int r = 0; r < 16; r++) {
                    int qp = (w + r) & 15;
                    int q0i = 2 * qp, q1i = 2 * qp + 1;
                    float4* Q0 = (float4*)(sj + q0i * 256);
                    float4* Q1 = (float4*)(sj + q1i * 256);
                    float v2[8], v3[8];
                    LDCOL(v2, Q0); LDCOL(v3, Q1);
                    float n0 = app0, n1 = app1, n2 = snj[q0i], n3 = snj[q1i];
                    float e01, e02, e03, e12, e13, e23;
                    DOTS6(rp0, rp1, v2, v3);
                    bool hit = false;
                    SOLVE4(rp0, rp1, v2, v3);
                    app0 = n0; app1 = n1;
                    if (hit) { STCOL(Q0, v2); STCOL(Q1, v3); }
                    if (lane == 0) {
                        snj[q0i] = n2; snj[q1i] = n3;
                        if (hit) { s_flag = 1; s_dirty = 1; s_any = 1; }
                    }
                    __syncthreads();
                }
                // store bj back + clean bookkeeping (s_dirty stable post-barrier)
                if (s_dirty) {
#pragma unroll
                    for (int h = 0; h < 2; h++) {
                        int col = w + 16 * h;
                        float4* dst = (float4*)(Bg + (bj * 32 + col) * 256);
                        const float4* src = (const float4*)(sj + col * 256);
                        dst[lane * 2] = src[lane * 2];
                        dst[lane * 2 + 1] = src[lane * 2 + 1];
                    }
                    if (t == 0) {
                        for (int k2 = 0; k2 < 8; k2++) {
                            s_clean[bi][k2] = 0; s_clean[k2][bi] = 0;
                            s_clean[bj][k2] = 0; s_clean[k2][bj] = 0;
                        }
                    }
                } else {
                    if (t == 0) { s_clean[bi][bj] = 1; s_clean[bj][bi] = 1; }
                }
                // settled by barrier at top of next bj iteration (or bi-end barrier)
            }
            __syncthreads();   // settle last phase's clean writes + sj reads
            // ---- store register columns back only if bi iteration rotated at all
            if (s_any) {
                float4* d0 = (float4*)(Bg + (bi * 32 + w) * 256);
                float4* d1 = (float4*)(Bg + (bi * 32 + w + 16) * 256);
                STCOL(d0, rp0);
                STCOL(d1, rp1);
            }
            __syncthreads();
        }
        __syncthreads();
        int done = (s_flag == 0);
        __syncthreads();
        if (done) break;
    }
}

// ---------------- stage 4: column norms, rank, keep factor ----------------
__global__ void k_fact() {
    int c = blockIdx.x, t = threadIdx.x, lane = t & 31, w = t >> 5;
    __shared__ float s2[256];
    const float* B = g_B + (size_t)c * HW;
    for (int j = w; j < 256; j += 8) {
        const float* col = B + j * 256;
        float a = 0.f;
#pragma unroll
        for (int m = 0; m < 8; m++) {
            float v = col[lane + 32 * m];
            a = fmaf(v, v, a);
        }
        a = warp_sum(a);
        if (lane == 0) s2[j] = a;
    }
    __syncthreads();
    float mys = s2[t];
    int kc = g_k[c];
    int rank = 0;
    for (int j = 0; j < 256; j++) {
        float v = s2[j];
        rank += (v > mys) || (v == mys && j < t);
    }
    g_fact[c * 256 + t] = (rank < kc) ? 1.0f / fmaxf(mys, 1e-20f) : 0.0f;
}

// ---------------- stage 5: T = diag(f) * B^T A  (C = M*N, M row-major = B^T) ----------
__global__ void __launch_bounds__(256) k_gemmT(const float* __restrict__ x) {
    int c = blockIdx.z;
    const float* M = g_B + (size_t)c * HW;   // M[j][i] = B(i,j)
    const float* N = x + (size_t)c * HW;     // A row-major
    float* C = g_T + (size_t)c * HW;
    int m0 = blockIdx.y * 64, n0 = blockIdx.x * 64;
    __shared__ float Ms[16][68], Ns[16][68];
    int t = threadIdx.x;
    int tx = t & 15, ty = t >> 4;
    float acc[4][4] = {};
    for (int k0 = 0; k0 < 256; k0 += 16) {
#pragma unroll
        for (int u = 0; u < 4; u++) {
            int id = t + 256 * u;
            int kk = id & 15, mm = id >> 4;
            Ms[kk][mm] = M[(m0 + mm) * 256 + k0 + kk];
        }
#pragma unroll
        for (int u = 0; u < 4; u++) {
            int id = t + 256 * u;
            int kk = id >> 6, nn = id & 63;
            Ns[kk][nn] = N[(k0 + kk) * 256 + n0 + nn];
        }
        __syncthreads();
#pragma unroll
        for (int kk = 0; kk < 16; kk++) {
            float a[4], b[4];
#pragma unroll
            for (int i = 0; i < 4; i++) a[i] = Ms[kk][ty * 4 + i];
#pragma unroll
            for (int j = 0; j < 4; j++) b[j] = Ns[kk][tx * 4 + j];
#pragma unroll
            for (int i = 0; i < 4; i++)
#pragma unroll
                for (int j = 0; j < 4; j++) acc[i][j] = fmaf(a[i], b[j], acc[i][j]);
        }
        __syncthreads();
    }
    const float* f = g_fact + c * 256;
#pragma unroll
    for (int i = 0; i < 4; i++) {
        float fi = f[m0 + ty * 4 + i];
#pragma unroll
        for (int j = 0; j < 4; j++)
            C[(m0 + ty * 4 + i) * 256 + n0 + tx * 4 + j] = acc[i][j] * fi;
    }
}

// ---------------- stage 6: R = B * T  (= M^T * N with M as above) ----------------
__global__ void __launch_bounds__(256) k_gemmR() {
    int c = blockIdx.z;
    const float* M = g_B + (size_t)c * HW;   // M[j][i] = B(i,j); need M^T * T
    const float* N = g_T + (size_t)c * HW;
    float* C = g_R + (size_t)c * HW;
    int m0 = blockIdx.y * 64, n0 = blockIdx.x * 64;
    __shared__ float Ms[16][68], Ns[16][68];
    int t = threadIdx.x;
    int tx = t & 15, ty = t >> 4;
    float acc[4][4] = {};
    for (int k0 = 0; k0 < 256; k0 += 16) {
#pragma unroll
        for (int u = 0; u < 4; u++) {
            int id = t + 256 * u;
            int kk = id >> 6, mm = id & 63;
            Ms[kk][mm] = M[(k0 + kk) * 256 + m0 + mm];   // M^T tile, coalesced
        }
#pragma unroll
        for (int u = 0; u < 4; u++) {
            int id = t + 256 * u;
            int kk = id >> 6, nn = id & 63;
            Ns[kk][nn] = N[(k0 + kk) * 256 + n0 + nn];
        }
        __syncthreads();
#pragma unroll
        for (int kk = 0; kk < 16; kk++) {
            float a[4], b[4];
#pragma unroll
            for (int i = 0; i < 4; i++) a[i] = Ms[kk][ty * 4 + i];
#pragma unroll
            for (int j = 0; j < 4; j++) b[j] = Ns[kk][tx * 4 + j];
#pragma unroll
            for (int i = 0; i < 4; i++)
#pragma unroll
                for (int j = 0; j < 4; j++) acc[i][j] = fmaf(a[i], b[j], acc[i][j]);
        }
        __syncthreads();
    }
#pragma unroll
    for (int i = 0; i < 4; i++)
#pragma unroll
        for (int j = 0; j < 4; j++)
            C[(m0 + ty * 4 + i) * 256 + n0 + tx * 4 + j] = acc[i][j];
}

// ---------------- stage 7: channel mean & max of recon ----------------
__global__ void k_avgmax() {
    int pix = blockIdx.x * 1024 + threadIdx.x;
    float s = 0.f, m = -3.4e38f;
    for (int c = 0; c < 256; c++) {
        float v = g_R[(size_t)c * HW + pix];
        s += v;
        m = fmaxf(m, v);
    }
    g_cat[pix]      = s * (1.0f / 256.0f);
    g_cat[HW + pix] = m;
}

// ---------------- stage 8: 7x7 conv (pad 3) + EPS clamp + sigmoid ----------------
__global__ void k_conv(const float* __restrict__ cw, float* __restrict__ out) {
    __shared__ float wsm[98];
    int tx = threadIdx.x, ty = threadIdx.y;
    int tid = ty * 32 + tx;
    if (tid < 98) wsm[tid] = cw[tid];
    __syncthreads();
    int gx = blockIdx.x * 32 + tx;
    int gy = blockIdx.y * 8 + ty;
    float acc = 0.f;
#pragma unroll
    for (int ci = 0; ci < 2; ci++) {
#pragma unroll
        for (int kh = 0; kh < 7; kh++) {
            int iy = gy + kh - 3;
            if (iy < 0 || iy > 255) continue;
#pragma unroll
            for (int kw = 0; kw < 7; kw++) {
                int ix = gx + kw - 3;
                if (ix < 0 || ix > 255) continue;
                acc = fmaf(g_cat[ci * HW + iy * 256 + ix], wsm[ci * 49 + kh * 7 + kw], acc);
            }
        }
    }
    const float EPSF = 2.220446049250313e-16f;
    if (acc < EPSF) acc = EPSF;
    out[gy * 256 + gx] = 1.0f / (1.0f + expf(-acc));
}

// ---------------- launch ----------------
extern "C" void kernel_launch(void* const* d_in, const int* in_sizes, int n_in,
                              void* d_out, int out_size) {
    const float* x  = (const float*)d_in[0];
    const float* w1 = (const float*)d_in[1];
    const float* w2 = (const float*)d_in[2];
    const float* cw = (const float*)d_in[3];
    const int*   kv = (const int*)d_in[4];

    k_stats<<<256, 256>>>(x);
    k_att<<<1, 256>>>(w1, w2, kv);
    k_tr<<<dim3(8, 8, 256), dim3(32, 8)>>>(x);
    k_jacobi<<<256, 512>>>();
    k_fact<<<256, 256>>>();
    k_gemmT<<<dim3(4, 4, 256), 256>>>(x);
    k_gemmR<<<dim3(4, 4, 256), 256>>>();
    k_avgmax<<<64, 1024>>>();
    k_conv<<<dim3(8, 32), dim3(32, 8)>>>(cw, (float*)d_out);
}

// round 17
// speedup vs baseline: 1.1074x; 1.1074x over previous
#include <cuda_runtime.h>
#include <math.h>

#define CC 256
#define HW 65536
#define NSWMAX 10
#define ROTTHR 4e-7f   // relative off-diag threshold^2

// ---- scratch (static device arrays; no allocation anywhere) ----
__device__ float g_B[CC * HW];   // 64MB: per-channel working matrix, column-major
__device__ float g_T[CC * HW];   // 64MB: T = diag(f) * B^T A
__device__ float g_R[CC * HW];   // 64MB: recon = B * T
__device__ float g_mean[CC];
__device__ float g_max[CC];
__device__ int   g_k[CC];
__device__ float g_fact[CC * CC];
__device__ float g_cat[2 * HW];

__device__ __forceinline__ float warp_sum(float a) {
#pragma unroll
    for (int o = 16; o > 0; o >>= 1) a += __shfl_xor_sync(0xFFFFFFFFu, a, o);
    return a;
}

// ---------------- stage 0: per-channel mean & max over HxW ----------------
__global__ void k_stats(const float* __restrict__ x) {
    int c = blockIdx.x, t = threadIdx.x;
    const float* xc = x + (size_t)c * HW;
    double s = 0.0;
    float m = -3.4e38f;
    for (int i = t; i < HW; i += 256) {
        float v = xc[i];
        s += (double)v;
        m = fmaxf(m, v);
    }
    __shared__ double ss[256];
    __shared__ float  sm[256];
    ss[t] = s; sm[t] = m;
    __syncthreads();
    for (int o = 128; o > 0; o >>= 1) {
        if (t < o) { ss[t] += ss[t + o]; sm[t] = fmaxf(sm[t], sm[t + o]); }
        __syncthreads();
    }
    if (t == 0) {
        g_mean[c] = (float)(ss[0] / (double)HW);
        g_max[c]  = sm[0];
    }
}

// ---------------- stage 1: channel attention -> k[c] ----------------
__global__ void k_att(const float* __restrict__ w1, const float* __restrict__ w2,
                      const int* __restrict__ kvp) {
    int t = threadIdx.x;
    __shared__ float  mu[256], mx[256];
    __shared__ double hA[16], hM[16];
    __shared__ double sy[256];
    __shared__ double ymin, ymax;
    mu[t] = g_mean[t]; mx[t] = g_max[t];
    __syncthreads();
    if (t < 16) {
        double a = 0.0, b = 0.0;
        for (int c2 = 0; c2 < 256; c2++) {
            double w = (double)w1[t * 256 + c2];
            a += w * (double)mu[c2];
            b += w * (double)mx[c2];
        }
        hA[t] = a > 0.0 ? a : 0.0;   // relu
        hM[t] = b > 0.0 ? b : 0.0;
    }
    __syncthreads();
    {
        double acc = 0.0;
        for (int r = 0; r < 16; r++)
            acc += (double)w2[t * 16 + r] * (hA[r] + hM[r]);
        sy[t] = 1.0 / (1.0 + exp(-acc));     // sigmoid(y_avg + y_max)
    }
    __syncthreads();
    if (t == 0) {
        double mn = sy[0], mv = sy[0];
        for (int i = 1; i < 256; i++) { mn = fmin(mn, sy[i]); mv = fmax(mv, sy[i]); }
        ymin = mn; ymax = mv;
    }
    __syncthreads();
    // kv hedge: accept int32 or float32 bit patterns
    int iv = *kvp;
    float fv = __int_as_float(iv);
    double kvd = (iv >= 0 && iv <= 1000000) ? (double)iv : (double)fv;
    double yc = (sy[t] - ymin) / (ymax - ymin + 1e-20);
    int k = (int)floor(256.0 * kvd * yc);
    if (k < 0) k = 0;
    if (k > 256) k = 256;
    g_k[t] = k;
}

// ---------------- stage 2: transpose x -> column-major B ----------------
__global__ void k_tr(const float* __restrict__ x) {
    __shared__ float tile[32][33];
    int c = blockIdx.z;
    int i0 = blockIdx.y * 32, j0 = blockIdx.x * 32;
    int tx = threadIdx.x, ty = threadIdx.y;
    const float* xc = x + (size_t)c * HW;
    float* bc = g_B + (size_t)c * HW;
#pragma unroll
    for (int m = 0; m < 4; m++)
        tile[ty + 8 * m][tx] = xc[(i0 + ty + 8 * m) * 256 + j0 + tx];
    __syncthreads();
#pragma unroll
    for (int m = 0; m < 4; m++)
        bc[(j0 + ty + 8 * m) * 256 + i0 + tx] = tile[tx][ty + 8 * m];
}

// load/store a 256-float column (8 per lane) as 2x float4
#define LDCOL(V, PTR)                                                          \
    { float4 _a = (PTR)[lane * 2], _b = (PTR)[lane * 2 + 1];                   \
      V[0]=_a.x; V[1]=_a.y; V[2]=_a.z; V[3]=_a.w;                              \
      V[4]=_b.x; V[5]=_b.y; V[6]=_b.z; V[7]=_b.w; }
#define STCOL(PTR, V)                                                          \
    { (PTR)[lane * 2]     = make_float4(V[0], V[1], V[2], V[3]);               \
      (PTR)[lane * 2 + 1] = make_float4(V[4], V[5], V[6], V[7]); }

// Jacobi rotation on columns (VI,VJ) with exact Gram tracking; sets FLAG+hit.
// NI/NJ diag entries, EIJ pivot; (EA,EB),(EC,ED) = (E[i][k],E[j][k]) cross terms.
#define ROT4F(VI, VJ, NI, NJ, EIJ, EA, EB, EC, ED, FLAG)                       \
    if ((EIJ) * (EIJ) > ROTTHR * (NI) * (NJ)) {                                \
        float tau = ((NJ) - (NI)) / (2.0f * (EIJ));                            \
        float tt  = copysignf(1.0f, tau) / (fabsf(tau) + sqrtf(1.0f + tau * tau)); \
        float cc  = 1.0f / sqrtf(1.0f + tt * tt);                              \
        float ss  = tt * cc;                                                   \
        _Pragma("unroll")                                                      \
        for (int m = 0; m < 8; m++) {                                          \
            float xp = VI[m];                                                  \
            VI[m] = fmaf(cc, xp, -ss * VJ[m]);                                 \
            VJ[m] = fmaf(ss, xp,  cc * VJ[m]);                                 \
        }                                                                      \
        (NI) -= tt * (EIJ); (NJ) += tt * (EIJ); (EIJ) = 0.0f;                  \
        float _ta = (EA); (EA) = fmaf(cc, _ta, -ss * (EB)); (EB) = fmaf(ss, _ta, cc * (EB)); \
        float _tc = (EC); (EC) = fmaf(cc, _tc, -ss * (ED)); (ED) = fmaf(ss, _tc, cc * (ED)); \
        FLAG = true; hit = true;                                               \
    }

// 6 pairwise dots of v0..v3, one interleaved warp reduction
#define DOTS6(V0, V1, V2, V3)                                                  \
    e01 = 0.f; e02 = 0.f; e03 = 0.f; e12 = 0.f; e13 = 0.f; e23 = 0.f;         \
    _Pragma("unroll")                                                          \
    for (int m = 0; m < 8; m++) {                                              \
        e01 = fmaf(V0[m], V1[m], e01); e02 = fmaf(V0[m], V2[m], e02);          \
        e03 = fmaf(V0[m], V3[m], e03); e12 = fmaf(V1[m], V2[m], e12);          \
        e13 = fmaf(V1[m], V3[m], e13); e23 = fmaf(V2[m], V3[m], e23);          \
    }                                                                          \
    _Pragma("unroll")                                                          \
    for (int o = 16; o > 0; o >>= 1) {                                         \
        e01 += __shfl_xor_sync(0xFFFFFFFFu, e01, o);                           \
        e02 += __shfl_xor_sync(0xFFFFFFFFu, e02, o);                           \
        e03 += __shfl_xor_sync(0xFFFFFFFFu, e03, o);                           \
        e12 += __shfl_xor_sync(0xFFFFFFFFu, e12, o);                           \
        e13 += __shfl_xor_sync(0xFFFFFFFFu, e13, o);                           \
        e23 += __shfl_xor_sync(0xFFFFFFFFu, e23, o);                           \
    }

// ---------------- stage 3: blocked one-sided Jacobi (Hestenes), no V ----------------
// 512 threads (16 warps), 2 CTAs/SM. 8 blocks of 32 columns.
// Intra-block: 31 tournament rounds x 16 warp-pairs in smem, cached norms (R14).
// Cross-block: warp holds reg cols (a=w, b=w+16); round r claims smem col pair
// (c=2*qp, d=2*qp+1), qp=(w+r)&15. ONE interleaved 6-dot reduction, then the
// 4 cross rotations (a,c),(b,d),(a,d),(b,c) with exact analytic Gram updates
// (no second reduction). Clean-pair matrix skips converged block pairs.
__global__ void __launch_bounds__(512, 2) k_jacobi() {
    int c = blockIdx.x;
    float* Bg = g_B + (size_t)c * HW;
    int t = threadIdx.x, lane = t & 31, w = t >> 5;   // w in 0..15

    __shared__ float sj[8192];     // 32KB: one 32-column block
    __shared__ float snj[32];      // column norms^2 of smem block
    __shared__ int s_flag;         // any rotation this sweep
    __shared__ int s_dirty;        // any rotation this phase
    __shared__ int s_any;          // any rotation this bi iteration
    __shared__ int s_skip;         // whole bi iteration clean
    __shared__ unsigned char s_clean[8][8];

    if (t < 64) s_clean[t >> 3][t & 7] = 0;
    __syncthreads();

    for (int sweep = 0; sweep < NSWMAX; sweep++) {
        if (t == 0) s_flag = 0;
        __syncthreads();
        for (int bi = 0; bi < 8; bi++) {
            // ---- whole-iteration skip check
            if (t == 0) {
                int ac = s_clean[bi][bi];
                for (int bj = bi + 1; bj < 8; bj++) ac &= s_clean[bi][bj];
                s_skip = ac;
            }
            __syncthreads();
            if (s_skip) continue;   // uniform

            // ---- load block bi: warp w loads cols w, w+16 + computes norms
#pragma unroll
            for (int h = 0; h < 2; h++) {
                int col = w + 16 * h;
                const float4* src = (const float4*)(Bg + (bi * 32 + col) * 256);
                float4* dst = (float4*)(sj + col * 256);
                float4 v0 = src[lane * 2], v1 = src[lane * 2 + 1];
                dst[lane * 2] = v0; dst[lane * 2 + 1] = v1;
                float a = v0.x*v0.x + v0.y*v0.y + v0.z*v0.z + v0.w*v0.w
                        + v1.x*v1.x + v1.y*v1.y + v1.z*v1.z + v1.w*v1.w;
                a = warp_sum(a);
                if (lane == 0) snj[col] = a;
            }
            if (t == 0) { s_any = 0; s_dirty = 0; }
            __syncthreads();

            // ---- intra-block tournament: 31 rounds x 16 pairs (R14 scheme)
            int do_intra = (s_clean[bi][bi] == 0);   // uniform, stable
            if (do_intra) {
                for (int r = 0; r < 31; r++) {
                    int p = (w == 0) ? 0 : 1 + (w - 1 + r) % 31;
                    int q = 1 + (30 - w + r) % 31;
                    float4* cp = (float4*)(sj + p * 256);
                    float4* cq = (float4*)(sj + q * 256);
                    float4 p0 = cp[lane * 2], p1 = cp[lane * 2 + 1];
                    float4 q0 = cq[lane * 2], q1 = cq[lane * 2 + 1];
                    float apq = p0.x * q0.x;
                    apq = fmaf(p0.y, q0.y, apq);
                    apq = fmaf(p0.z, q0.z, apq);
                    apq = fmaf(p0.w, q0.w, apq);
                    apq = fmaf(p1.x, q1.x, apq);
                    apq = fmaf(p1.y, q1.y, apq);
                    apq = fmaf(p1.z, q1.z, apq);
                    apq = fmaf(p1.w, q1.w, apq);
                    apq = warp_sum(apq);
                    float app = snj[p], aqq = snj[q];
                    if (apq * apq > ROTTHR * app * aqq) {
                        float tau = (aqq - app) / (2.0f * apq);
                        float tt  = copysignf(1.0f, tau) / (fabsf(tau) + sqrtf(1.0f + tau * tau));
                        float cth = 1.0f / sqrtf(1.0f + tt * tt);
                        float sth = tt * cth;
                        float4 np, nq;
                        np.x = cth*p0.x - sth*q0.x;  nq.x = sth*p0.x + cth*q0.x;
                        np.y = cth*p0.y - sth*q0.y;  nq.y = sth*p0.y + cth*q0.y;
                        np.z = cth*p0.z - sth*q0.z;  nq.z = sth*p0.z + cth*q0.z;
                        np.w = cth*p0.w - sth*q0.w;  nq.w = sth*p0.w + cth*q0.w;
                        cp[lane * 2] = np;  cq[lane * 2] = nq;
                        np.x = cth*p1.x - sth*q1.x;  nq.x = sth*p1.x + cth*q1.x;
                        np.y = cth*p1.y - sth*q1.y;  nq.y = sth*p1.y + cth*q1.y;
                        np.z = cth*p1.z - sth*q1.z;  nq.z = sth*p1.z + cth*q1.z;
                        np.w = cth*p1.w - sth*q1.w;  nq.w = sth*p1.w + cth*q1.w;
                        cp[lane * 2 + 1] = np;  cq[lane * 2 + 1] = nq;
                        if (lane == 0) {
                            snj[p] = app - tt * apq;
                            snj[q] = aqq + tt * apq;
                            s_flag = 1; s_any = 1; s_dirty = 1;
                        }
                    }
                    __syncthreads();
                }
                // clean-matrix update from intra result (s_dirty stable post-barrier)
                if (t == 0) {
                    if (s_dirty) {
                        for (int k2 = 0; k2 < 8; k2++) { s_clean[bi][k2] = 0; s_clean[k2][bi] = 0; }
                    } else {
                        s_clean[bi][bi] = 1;
                    }
                }
                // settled by the barrier at top of bj loop below
            }

            // ---- move cols w and w+16 of bi into registers (exact norms)
            float rp0[8], rp1[8], app0, app1;
            {
                const float4* c0 = (const float4*)(sj + w * 256);
                LDCOL(rp0, c0);
                float a = 0.f;
#pragma unroll
                for (int m = 0; m < 8; m++) a = fmaf(rp0[m], rp0[m], a);
                app0 = warp_sum(a);
                const float4* c1 = (const float4*)(sj + (w + 16) * 256);
                LDCOL(rp1, c1);
                float b = 0.f;
#pragma unroll
                for (int m = 0; m < 8; m++) b = fmaf(rp1[m], rp1[m], b);
                app1 = warp_sum(b);
            }

            // ---- cross-block phases
            for (int bj = bi + 1; bj < 8; bj++) {
                __syncthreads();   // settle clean-matrix writes from prior phase/intra
                int do_cross = (s_clean[bi][bj] == 0);   // uniform
                if (!do_cross) continue;

                // load bj (own cols — same-warp ordering vs. prior reads)
#pragma unroll
                for (int h = 0; h < 2; h++) {
                    int col = w + 16 * h;
                    const float4* src = (const float4*)(Bg + (bj * 32 + col) * 256);
                    float4* dst = (float4*)(sj + col * 256);
                    float4 v0 = src[lane * 2], v1 = src[lane * 2 + 1];
                    dst[lane * 2] = v0; dst[lane * 2 + 1] = v1;
                    float a = v0.x*v0.x + v0.y*v0.y + v0.z*v0.z + v0.w*v0.w
                            + v1.x*v1.x + v1.y*v1.y + v1.z*v1.z + v1.w*v1.w;
                    a = warp_sum(a);
                    if (lane == 0) snj[col] = a;
                }
                if (t == 0) s_dirty = 0;
                __syncthreads();

                // 16 rounds; warp claims smem col pair (2*qp, 2*qp+1)
                for (int r = 0; r < 16; r++) {
                    int qp = (w + r) & 15;
                    int q0i = 2 * qp, q1i = 2 * qp + 1;
                    float4* Q0 = (float4*)(sj + q0i * 256);
                    float4* Q1 = (float4*)(sj + q1i * 256);
                    float v2[8], v3[8];
                    LDCOL(v2, Q0); LDCOL(v3, Q1);
                    float n0 = app0, n1 = app1, n2 = snj[q0i], n3 = snj[q1i];
                    float e01, e02, e03, e12, e13, e23;
                    DOTS6(rp0, rp1, v2, v3);
                    bool hit = false, wr0 = false, wr1 = false;
                    // R14's 4 cross rotations, Gram updated analytically:
                    ROT4F(rp0, v2, n0, n2, e02, e01, e12, e03, e23, wr0);
                    ROT4F(rp1, v3, n1, n3, e13, e01, e03, e12, e23, wr1);
                    ROT4F(rp0, v3, n0, n3, e03, e01, e13, e02, e23, wr1);
                    ROT4F(rp1, v2, n1, n2, e12, e01, e02, e13, e23, wr0);
                    app0 = n0; app1 = n1;
                    if (wr0) STCOL(Q0, v2);
                    if (wr1) STCOL(Q1, v3);
                    if (lane == 0) {
                        snj[q0i] = n2; snj[q1i] = n3;
                        if (hit) { s_flag = 1; s_dirty = 1; s_any = 1; }
                    }
                    __syncthreads();
                }
                // store bj back + clean bookkeeping (s_dirty stable post-barrier)
                if (s_dirty) {
#pragma unroll
                    for (int h = 0; h < 2; h++) {
                        int col = w + 16 * h;
                        float4* dst = (float4*)(Bg + (bj * 32 + col) * 256);
                        const float4* src = (const float4*)(sj + col * 256);
                        dst[lane * 2] = src[lane * 2];
                        dst[lane * 2 + 1] = src[lane * 2 + 1];
                    }
                    if (t == 0) {
                        for (int k2 = 0; k2 < 8; k2++) {
                            s_clean[bi][k2] = 0; s_clean[k2][bi] = 0;
                            s_clean[bj][k2] = 0; s_clean[k2][bj] = 0;
                        }
                    }
                } else {
                    if (t == 0) { s_clean[bi][bj] = 1; s_clean[bj][bi] = 1; }
                }
                // settled by barrier at top of next bj iteration (or bi-end barrier)
            }
            __syncthreads();   // settle last phase's clean writes + sj reads
            // ---- store register columns back only if bi iteration rotated at all
            if (s_any) {
                float4* d0 = (float4*)(Bg + (bi * 32 + w) * 256);
                float4* d1 = (float4*)(Bg + (bi * 32 + w + 16) * 256);
                STCOL(d0, rp0);
                STCOL(d1, rp1);
            }
            __syncthreads();
        }
        __syncthreads();
        int done = (s_flag == 0);
        __syncthreads();
        if (done) break;
    }
}

// ---------------- stage 4: column norms, rank, keep factor ----------------
__global__ void k_fact() {
    int c = blockIdx.x, t = threadIdx.x, lane = t & 31, w = t >> 5;
    __shared__ float s2[256];
    const float* B = g_B + (size_t)c * HW;
    for (int j = w; j < 256; j += 8) {
        const float* col = B + j * 256;
        float a = 0.f;
#pragma unroll
        for (int m = 0; m < 8; m++) {
            float v = col[lane + 32 * m];
            a = fmaf(v, v, a);
        }
        a = warp_sum(a);
        if (lane == 0) s2[j] = a;
    }
    __syncthreads();
    float mys = s2[t];
    int kc = g_k[c];
    int rank = 0;
    for (int j = 0; j < 256; j++) {
        float v = s2[j];
        rank += (v > mys) || (v == mys && j < t);
    }
    g_fact[c * 256 + t] = (rank < kc) ? 1.0f / fmaxf(mys, 1e-20f) : 0.0f;
}

// ---------------- stage 5: T = diag(f) * B^T A  (C = M*N, M row-major = B^T) ----------
__global__ void __launch_bounds__(256) k_gemmT(const float* __restrict__ x) {
    int c = blockIdx.z;
    const float* M = g_B + (size_t)c * HW;   // M[j][i] = B(i,j)
    const float* N = x + (size_t)c * HW;     // A row-major
    float* C = g_T + (size_t)c * HW;
    int m0 = blockIdx.y * 64, n0 = blockIdx.x * 64;
    __shared__ float Ms[16][68], Ns[16][68];
    int t = threadIdx.x;
    int tx = t & 15, ty = t >> 4;
    float acc[4][4] = {};
    for (int k0 = 0; k0 < 256; k0 += 16) {
#pragma unroll
        for (int u = 0; u < 4; u++) {
            int id = t + 256 * u;
            int kk = id & 15, mm = id >> 4;
            Ms[kk][mm] = M[(m0 + mm) * 256 + k0 + kk];
        }
#pragma unroll
        for (int u = 0; u < 4; u++) {
            int id = t + 256 * u;
            int kk = id >> 6, nn = id & 63;
            Ns[kk][nn] = N[(k0 + kk) * 256 + n0 + nn];
        }
        __syncthreads();
#pragma unroll
        for (int kk = 0; kk < 16; kk++) {
            float a[4], b[4];
#pragma unroll
            for (int i = 0; i < 4; i++) a[i] = Ms[kk][ty * 4 + i];
#pragma unroll
            for (int j = 0; j < 4; j++) b[j] = Ns[kk][tx * 4 + j];
#pragma unroll
            for (int i = 0; i < 4; i++)
#pragma unroll
                for (int j = 0; j < 4; j++) acc[i][j] = fmaf(a[i], b[j], acc[i][j]);
        }
        __syncthreads();
    }
    const float* f = g_fact + c * 256;
#pragma unroll
    for (int i = 0; i < 4; i++) {
        float fi = f[m0 + ty * 4 + i];
#pragma unroll
        for (int j = 0; j < 4; j++)
            C[(m0 + ty * 4 + i) * 256 + n0 + tx * 4 + j] = acc[i][j] * fi;
    }
}

// ---------------- stage 6: R = B * T  (= M^T * N with M as above) ----------------
__global__ void __launch_bounds__(256) k_gemmR() {
    int c = blockIdx.z;
    const float* M = g_B + (size_t)c * HW;   // M[j][i] = B(i,j); need M^T * T
    const float* N = g_T + (size_t)c * HW;
    float* C = g_R + (size_t)c * HW;
    int m0 = blockIdx.y * 64, n0 = blockIdx.x * 64;
    __shared__ float Ms[16][68], Ns[16][68];
    int t = threadIdx.x;
    int tx = t & 15, ty = t >> 4;
    float acc[4][4] = {};
    for (int k0 = 0; k0 < 256; k0 += 16) {
#pragma unroll
        for (int u = 0; u < 4; u++) {
            int id = t + 256 * u;
            int kk = id >> 6, mm = id & 63;
            Ms[kk][mm] = M[(k0 + kk) * 256 + m0 + mm];   // M^T tile, coalesced
        }
#pragma unroll
        for (int u = 0; u < 4; u++) {
            int id = t + 256 * u;
            int kk = id >> 6, nn = id & 63;
            Ns[kk][nn] = N[(k0 + kk) * 256 + n0 + nn];
        }
        __syncthreads();
#pragma unroll
        for (int kk = 0; kk < 16; kk++) {
            float a[4], b[4];
#pragma unroll
            for (int i = 0; i < 4; i++) a[i] = Ms[kk][ty * 4 + i];
#pragma unroll
            for (int j = 0; j < 4; j++) b[j] = Ns[kk][tx * 4 + j];
#pragma unroll
            for (int i = 0; i < 4; i++)
#pragma unroll
                for (int j = 0; j < 4; j++) acc[i][j] = fmaf(a[i], b[j], acc[i][j]);
        }
        __syncthreads();
    }
#pragma unroll
    for (int i = 0; i < 4; i++)
#pragma unroll
        for (int j = 0; j < 4; j++)
            C[(m0 + ty * 4 + i) * 256 + n0 + tx * 4 + j] = acc[i][j];
}

// ---------------- stage 7: channel mean & max of recon ----------------
__global__ void k_avgmax() {
    int pix = blockIdx.x * 1024 + threadIdx.x;
    float s = 0.f, m = -3.4e38f;
    for (int c = 0; c < 256; c++) {
        float v = g_R[(size_t)c * HW + pix];
        s += v;
        m = fmaxf(m, v);
    }
    g_cat[pix]      = s * (1.0f / 256.0f);
    g_cat[HW + pix] = m;
}

// ---------------- stage 8: 7x7 conv (pad 3) + EPS clamp + sigmoid ----------------
__global__ void k_conv(const float* __restrict__ cw, float* __restrict__ out) {
    __shared__ float wsm[98];
    int tx = threadIdx.x, ty = threadIdx.y;
    int tid = ty * 32 + tx;
    if (tid < 98) wsm[tid] = cw[tid];
    __syncthreads();
    int gx = blockIdx.x * 32 + tx;
    int gy = blockIdx.y * 8 + ty;
    float acc = 0.f;
#pragma unroll
    for (int ci = 0; ci < 2; ci++) {
#pragma unroll
        for (int kh = 0; kh < 7; kh++) {
            int iy = gy + kh - 3;
            if (iy < 0 || iy > 255) continue;
#pragma unroll
            for (int kw = 0; kw < 7; kw++) {
                int ix = gx + kw - 3;
                if (ix < 0 || ix > 255) continue;
                acc = fmaf(g_cat[ci * HW + iy * 256 + ix], wsm[ci * 49 + kh * 7 + kw], acc);
            }
        }
    }
    const float EPSF = 2.220446049250313e-16f;
    if (acc < EPSF) acc = EPSF;
    out[gy * 256 + gx] = 1.0f / (1.0f + expf(-acc));
}

// ---------------- launch ----------------
extern "C" void kernel_launch(void* const* d_in, const int* in_sizes, int n_in,
                              void* d_out, int out_size) {
    const float* x  = (const float*)d_in[0];
    const float* w1 = (const float*)d_in[1];
    const float* w2 = (const float*)d_in[2];
    const float* cw = (const float*)d_in[3];
    const int*   kv = (const int*)d_in[4];

    k_stats<<<256, 256>>>(x);
    k_att<<<1, 256>>>(w1, w2, kv);
    k_tr<<<dim3(8, 8, 256), dim3(32, 8)>>>(x);
    k_jacobi<<<256, 512>>>();
    k_fact<<<256, 256>>>();
    k_gemmT<<<dim3(4, 4, 256), 256>>>(x);
    k_gemmR<<<dim3(4, 4, 256), 256>>>();
    k_avgmax<<<64, 1024>>>();
    k_conv<<<dim3(8, 32), dim3(32, 8)>>>(cw, (float*)d_out);
}